// round 12
// baseline (speedup 1.0000x reference)
#include <cuda_runtime.h>
#include <cstdint>

#define NTOK  1024
#define DS    384
#define DP    128
#define NH    16
#define DH    64
#define INNER 1024
#define NN    (NTOK*NTOK)

// ---------------- scratch ----------------
__device__ float g_q[NTOK*INNER];           // tf32-rounded
__device__ float g_k[NTOK*INNER];           // tf32-rounded
__device__ float g_v[NTOK*INNER];           // tf32-rounded
__device__ float g_g[NTOK*INNER];           // full fp32 (gate)
__device__ float g_scores[(size_t)NH*NN];
__device__ float g_attnout[NTOK*INNER];     // attnout * sigmoid(gate)
__device__ float g_gw[NH*DP];
__device__ float g_T[NH];
__device__ float g_U[NH];

__device__ __forceinline__ float to_tf32(float x) {
    float y;
    asm("cvt.rna.tf32.f32 %0, %1;" : "=f"(y) : "f"(x));
    return y;
}
__device__ __forceinline__ void mma_tf32(float c[4],
    uint32_t a0, uint32_t a1, uint32_t a2, uint32_t a3,
    uint32_t b0, uint32_t b1)
{
    asm volatile("mma.sync.aligned.m16n8k8.row.col.f32.tf32.tf32.f32 "
        "{%0,%1,%2,%3}, {%4,%5,%6,%7}, {%8,%9}, {%0,%1,%2,%3};"
        : "+f"(c[0]), "+f"(c[1]), "+f"(c[2]), "+f"(c[3])
        : "r"(a0), "r"(a1), "r"(a2), "r"(a3), "r"(b0), "r"(b1));
}
__device__ __forceinline__ void cp16(float* dst, const float* src) {
    uint32_t s = (uint32_t)__cvta_generic_to_shared(dst);
    asm volatile("cp.async.cg.shared.global [%0], [%1], 16;" :: "r"(s), "l"(src));
}
#define CP_COMMIT() asm volatile("cp.async.commit_group;")

// ---------------- K0: tiny precompute ----------------
__global__ void prep_kernel(const float* __restrict__ gamma,
                            const float* __restrict__ beta,
                            const float* __restrict__ Wb)
{
    int t = threadIdx.x;
    for (int l = t; l < NH*DP; l += blockDim.x) {
        int h = l / DP, d = l % DP;
        g_gw[h*DP + d] = gamma[d] * Wb[d*NH + h];
    }
    if (t < 2*NH) {
        int h = t % NH;
        const float* src = (t < NH) ? gamma : beta;
        float s = 0.f;
        for (int d = 0; d < DP; d++) s += src[d] * Wb[d*NH + h];
        if (t < NH) g_T[h] = s; else g_U[h] = s;
    }
}

// ---------------- fused proj(4x) + bias kernel ----------------
#define AS_S 20
#define BS_S 72
#define WS_S 24
#define T_S  36

__device__ __forceinline__ void proj_body(float* smem,
    const float* __restrict__ X, const float* __restrict__ B,
    const float* __restrict__ bq, int sel, int bx, int by)
{
    float* As = smem;
    float* Bs = smem + 64*AS_S;
    float* C = (sel==0) ? g_q : (sel==1) ? g_k : (sel==2) ? g_v : g_g;

    const int t = threadIdx.x;
    const int m0 = by * 64;
    const int n0 = bx * 64;
    const int wid = t >> 5, lane = t & 31;
    const int wm = wid & 1, wn = wid >> 1;
    const int g = lane >> 2, tig = lane & 3;
    const int R0 = wm * 32, C0 = wn * 16;

    float c[2][2][4];
    #pragma unroll
    for (int mt = 0; mt < 2; mt++)
        #pragma unroll
        for (int nt = 0; nt < 2; nt++)
            #pragma unroll
            for (int j = 0; j < 4; j++) c[mt][nt][j] = 0.f;

    const int am = t >> 2, akq = (t & 3) * 4;
    const int bk = t >> 4, bn4 = (t & 15) * 4;

    for (int k0 = 0; k0 < DS; k0 += 16) {
        {
            float4 av = *(const float4*)(X + (size_t)(m0+am)*DS + k0 + akq);
            float* d = As + am*AS_S + akq;
            d[0]=to_tf32(av.x); d[1]=to_tf32(av.y); d[2]=to_tf32(av.z); d[3]=to_tf32(av.w);
        }
        {
            float4 bv = *(const float4*)(B + (size_t)(k0+bk)*INNER + n0 + bn4);
            float* d = Bs + bk*BS_S + bn4;
            d[0]=to_tf32(bv.x); d[1]=to_tf32(bv.y); d[2]=to_tf32(bv.z); d[3]=to_tf32(bv.w);
        }
        __syncthreads();
        #pragma unroll
        for (int kk = 0; kk < 2; kk++) {
            int kb = kk * 8;
            uint32_t b0[2], b1[2];
            #pragma unroll
            for (int nt = 0; nt < 2; nt++) {
                b0[nt] = __float_as_uint(Bs[(kb+tig  )*BS_S + C0 + nt*8 + g]);
                b1[nt] = __float_as_uint(Bs[(kb+tig+4)*BS_S + C0 + nt*8 + g]);
            }
            #pragma unroll
            for (int mt = 0; mt < 2; mt++) {
                uint32_t a0 = __float_as_uint(As[(R0+mt*16+g  )*AS_S + kb+tig]);
                uint32_t a1 = __float_as_uint(As[(R0+mt*16+g+8)*AS_S + kb+tig]);
                uint32_t a2 = __float_as_uint(As[(R0+mt*16+g  )*AS_S + kb+tig+4]);
                uint32_t a3 = __float_as_uint(As[(R0+mt*16+g+8)*AS_S + kb+tig+4]);
                #pragma unroll
                for (int nt = 0; nt < 2; nt++)
                    mma_tf32(c[mt][nt], a0, a1, a2, a3, b0[nt], b1[nt]);
            }
        }
        __syncthreads();
    }

    #pragma unroll
    for (int mt = 0; mt < 2; mt++) {
        #pragma unroll
        for (int nt = 0; nt < 2; nt++) {
            int n = n0 + C0 + nt*8 + tig*2;
            float bx2 = 0.f, by2 = 0.f;
            if (sel == 0) { bx2 = bq[n]; by2 = bq[n+1]; }
            int r0 = m0 + R0 + mt*16 + g;
            float v00 = c[mt][nt][0]+bx2, v01 = c[mt][nt][1]+by2;
            float v10 = c[mt][nt][2]+bx2, v11 = c[mt][nt][3]+by2;
            if (sel < 3) {   // q,k,v pre-rounded to tf32 (idempotent vs consumer-side round)
                v00 = to_tf32(v00); v01 = to_tf32(v01);
                v10 = to_tf32(v10); v11 = to_tf32(v11);
            }
            *(float2*)(C + (size_t)r0*INNER + n)     = make_float2(v00, v01);
            *(float2*)(C + (size_t)(r0+8)*INNER + n) = make_float2(v10, v11);
        }
    }
}

__device__ __forceinline__ void bias_stage(float* T, const float* pw, size_t pb,
                                           int chunk, int t)
{
    const int srow = t >> 3, sc4 = (t & 7) * 4;
    float* dst = T + (chunk % 3) * 128*T_S;
    #pragma unroll
    for (int i = 0; i < 4; i++) {
        int row = srow + i*32;
        cp16(&dst[row*T_S + sc4], pw + (pb+row)*DP + chunk*32 + sc4);
    }
    CP_COMMIT();
}

__device__ __forceinline__ void bias_body(float* smem,
    const float* __restrict__ pw, const float* __restrict__ ab, int bid)
{
    float* Ws = smem;               // 128*WS_S
    float* T  = smem + 128*WS_S;    // 3 * 128*T_S

    const int t = threadIdx.x;
    const size_t pb = (size_t)bid * 128;

    bias_stage(T, pw, pb, 0, t);

    for (int l = t; l < 16*128; l += 256) {
        int h = l >> 7, d = l & 127;
        Ws[d*WS_S + h] = to_tf32(g_gw[h*DP + d]);
    }

    bias_stage(T, pw, pb, 1, t);

    const int wid = t >> 5, lane = t & 31;
    const int g = lane >> 2, tig = lane & 3;
    const int r0 = wid*16 + g;

    float c[2][4];
    #pragma unroll
    for (int nt = 0; nt < 2; nt++)
        #pragma unroll
        for (int j = 0; j < 4; j++) c[nt][j] = 0.f;
    float s0 = 0.f, q0 = 0.f, s1 = 0.f, q1 = 0.f;

    for (int cc = 0; cc < 4; cc++) {
        if (cc + 2 < 4) bias_stage(T, pw, pb, cc + 2, t);
        if (cc <= 1)      asm volatile("cp.async.wait_group 2;");
        else if (cc == 2) asm volatile("cp.async.wait_group 1;");
        else              asm volatile("cp.async.wait_group 0;");
        __syncthreads();
        float* Tb = T + (cc % 3) * 128*T_S;

        #pragma unroll
        for (int ks = 0; ks < 4; ks++) {
            int kb = ks*8;
            float a0 = Tb[(r0  )*T_S + kb+tig];
            float a1 = Tb[(r0+8)*T_S + kb+tig];
            float a2 = Tb[(r0  )*T_S + kb+tig+4];
            float a3 = Tb[(r0+8)*T_S + kb+tig+4];
            s0 += a0 + a2;  q0 += a0*a0 + a2*a2;
            s1 += a1 + a3;  q1 += a1*a1 + a3*a3;
            uint32_t u0 = __float_as_uint(to_tf32(a0));
            uint32_t u1 = __float_as_uint(to_tf32(a1));
            uint32_t u2 = __float_as_uint(to_tf32(a2));
            uint32_t u3 = __float_as_uint(to_tf32(a3));
            int kg = cc*32 + kb;
            #pragma unroll
            for (int nt = 0; nt < 2; nt++) {
                uint32_t b0 = __float_as_uint(Ws[(kg+tig  )*WS_S + nt*8 + g]);
                uint32_t b1 = __float_as_uint(Ws[(kg+tig+4)*WS_S + nt*8 + g]);
                mma_tf32(c[nt], u0, u1, u2, u3, b0, b1);
            }
        }
        __syncthreads();
    }

    s0 += __shfl_xor_sync(0xffffffffu, s0, 1); s0 += __shfl_xor_sync(0xffffffffu, s0, 2);
    q0 += __shfl_xor_sync(0xffffffffu, q0, 1); q0 += __shfl_xor_sync(0xffffffffu, q0, 2);
    s1 += __shfl_xor_sync(0xffffffffu, s1, 1); s1 += __shfl_xor_sync(0xffffffffu, s1, 2);
    q1 += __shfl_xor_sync(0xffffffffu, q1, 1); q1 += __shfl_xor_sync(0xffffffffu, q1, 2);

    float mu0 = s0 * (1.f/DP), mu1 = s1 * (1.f/DP);
    float rinv0 = rsqrtf(q0*(1.f/DP) - mu0*mu0 + 1e-5f);
    float rinv1 = rsqrtf(q1*(1.f/DP) - mu1*mu1 + 1e-5f);
    float ab0 = ab[pb + r0], ab1 = ab[pb + r0 + 8];

    float* Ss = T;
    #pragma unroll
    for (int nt = 0; nt < 2; nt++) {
        #pragma unroll
        for (int j = 0; j < 2; j++) {
            int h = nt*8 + tig*2 + j;
            float Th = g_T[h], Uh = g_U[h];
            Ss[(r0    )*17 + h] = rinv0*(c[nt][j  ] - mu0*Th) + Uh + ab0;
            Ss[(r0 + 8)*17 + h] = rinv1*(c[nt][2+j] - mu1*Th) + Uh + ab1;
        }
    }
    __syncthreads();
    for (int l = t; l < 2048; l += 256) {
        int h = l >> 7, r = l & 127;
        g_scores[(size_t)h*NN + pb + r] = Ss[r*17 + h];
    }
}

__global__ __launch_bounds__(256) void fused_pb_kernel(
    const float* __restrict__ X,
    const float* __restrict__ Wq, const float* __restrict__ bq,
    const float* __restrict__ Wk, const float* __restrict__ Wv,
    const float* __restrict__ Wg,
    const float* __restrict__ pw, const float* __restrict__ ab)
{
    extern __shared__ float smem[];
    int bid = blockIdx.x;
    if (bid < 1024) {
        int sel = bid >> 8;
        int rem = bid & 255;
        const float* B = (sel==0) ? Wq : (sel==1) ? Wk : (sel==2) ? Wv : Wg;
        proj_body(smem, X, B, bq, sel, rem & 15, rem >> 4);
    } else {
        bias_body(smem, pw, ab, bid - 1024);
    }
}

// ---------------- attn v3: fully cp.async (K/V/bias double-buffered, no cvt) ----------------
#define KS  68
#define VS  72
#define BBS 68
#define PSS 68

__device__ __forceinline__ void attn_stage(float* Kc, float* Vc, float* Bc,
    const float* bsrc, int h, int c, int t)
{
    const int buf = c & 1;
    const int jc = c * 64;
    float* Kb = Kc + buf*64*KS;
    float* Vb = Vc + buf*64*VS;
    float* Bb = Bc + buf*128*BBS;
    const int kr = t >> 2, kc0 = (t & 3) * 16;
    const float* ks = g_k + (size_t)(jc+kr)*INNER + h*DH + kc0;
    const float* vs = g_v + (size_t)(jc+kr)*INNER + h*DH + kc0;
    #pragma unroll
    for (int u = 0; u < 4; u++) cp16(Kb + kr*KS + kc0 + u*4, ks + u*4);
    #pragma unroll
    for (int u = 0; u < 4; u++) cp16(Vb + kr*VS + kc0 + u*4, vs + u*4);
    const int br = t >> 1, bc0 = (t & 1) * 32;
    const float* bs = bsrc + (size_t)br*NTOK + jc + bc0;
    #pragma unroll
    for (int u = 0; u < 8; u++) cp16(Bb + br*BBS + bc0 + u*4, bs + u*4);
    CP_COMMIT();
}

__global__ __launch_bounds__(256, 1) void attn3_kernel()
{
    extern __shared__ float sm2[];
    float* Kc = sm2;                    // 2 * 64*KS
    float* Vc = Kc + 2*64*KS;           // 2 * 64*VS
    float* Bc = Vc + 2*64*VS;           // 2 * 128*BBS
    float* Ps = Bc + 2*128*BBS;         // 128*PSS

    const int t = threadIdx.x;
    const int h = blockIdx.y;
    const int i0 = blockIdx.x * 128;
    const int wid = t >> 5, lane = t & 31;
    const int g = lane >> 2, tig = lane & 3;
    const int R0 = wid * 16;
    const float* bsrc = g_scores + (size_t)h * NN + (size_t)i0 * NTOK;

    attn_stage(Kc, Vc, Bc, bsrc, h, 0, t);

    // Q fragments (g_q pre-rounded tf32)
    uint32_t qf[8][4];
    {
        const float* q0 = g_q + (size_t)(i0 + R0 + g    ) * INNER + h*DH;
        const float* q1 = g_q + (size_t)(i0 + R0 + g + 8) * INNER + h*DH;
        #pragma unroll
        for (int kk = 0; kk < 8; kk++) {
            qf[kk][0] = __float_as_uint(q0[kk*8 + tig]);
            qf[kk][1] = __float_as_uint(q1[kk*8 + tig]);
            qf[kk][2] = __float_as_uint(q0[kk*8 + tig + 4]);
            qf[kk][3] = __float_as_uint(q1[kk*8 + tig + 4]);
        }
    }

    attn_stage(Kc, Vc, Bc, bsrc, h, 1, t);

    float oc[8][4];
    #pragma unroll
    for (int nt = 0; nt < 8; nt++)
        #pragma unroll
        for (int j = 0; j < 4; j++) oc[nt][j] = 0.f;
    float m0v = -1e30f, m1v = -1e30f, l0v = 0.f, l1v = 0.f;

    for (int c = 0; c < 16; c++) {
        if (c < 15) asm volatile("cp.async.wait_group 1;");
        else        asm volatile("cp.async.wait_group 0;");
        __syncthreads();
        const float* Kb = Kc + (c&1)*64*KS;
        const float* Vb = Vc + (c&1)*64*VS;
        const float* Bcur = Bc + (c&1)*128*BBS;

        // ---- S = Q K^T ----
        float sc[8][4];
        #pragma unroll
        for (int nt = 0; nt < 8; nt++)
            #pragma unroll
            for (int j = 0; j < 4; j++) sc[nt][j] = 0.f;
        #pragma unroll
        for (int kk = 0; kk < 8; kk++) {
            #pragma unroll
            for (int nt = 0; nt < 8; nt++) {
                uint32_t b0 = __float_as_uint(Kb[(nt*8+g)*KS + kk*8+tig]);
                uint32_t b1 = __float_as_uint(Kb[(nt*8+g)*KS + kk*8+tig+4]);
                mma_tf32(sc[nt], qf[kk][0], qf[kk][1], qf[kk][2], qf[kk][3], b0, b1);
            }
        }

        // ---- scale + bias + warp-local row max ----
        float rm0 = -1e30f, rm1 = -1e30f;
        #pragma unroll
        for (int nt = 0; nt < 8; nt++) {
            int cb = nt*8 + tig*2;
            sc[nt][0] = sc[nt][0]*0.125f + Bcur[(R0+g  )*BBS + cb];
            sc[nt][1] = sc[nt][1]*0.125f + Bcur[(R0+g  )*BBS + cb+1];
            sc[nt][2] = sc[nt][2]*0.125f + Bcur[(R0+g+8)*BBS + cb];
            sc[nt][3] = sc[nt][3]*0.125f + Bcur[(R0+g+8)*BBS + cb+1];
            rm0 = fmaxf(rm0, fmaxf(sc[nt][0], sc[nt][1]));
            rm1 = fmaxf(rm1, fmaxf(sc[nt][2], sc[nt][3]));
        }
        rm0 = fmaxf(rm0, __shfl_xor_sync(0xffffffffu, rm0, 1));
        rm0 = fmaxf(rm0, __shfl_xor_sync(0xffffffffu, rm0, 2));
        rm1 = fmaxf(rm1, __shfl_xor_sync(0xffffffffu, rm1, 1));
        rm1 = fmaxf(rm1, __shfl_xor_sync(0xffffffffu, rm1, 2));

        float mn0 = fmaxf(m0v, rm0), mn1 = fmaxf(m1v, rm1);
        float al0 = __expf(m0v - mn0), al1 = __expf(m1v - mn1);
        m0v = mn0; m1v = mn1;

        float ls0 = 0.f, ls1 = 0.f;
        #pragma unroll
        for (int nt = 0; nt < 8; nt++) {
            int cb = nt*8 + tig*2;
            float p0 = __expf(sc[nt][0] - mn0);
            float p1 = __expf(sc[nt][1] - mn0);
            float p2 = __expf(sc[nt][2] - mn1);
            float p3 = __expf(sc[nt][3] - mn1);
            ls0 += p0 + p1; ls1 += p2 + p3;
            Ps[(R0+g  )*PSS + cb  ] = to_tf32(p0);
            Ps[(R0+g  )*PSS + cb+1] = to_tf32(p1);
            Ps[(R0+g+8)*PSS + cb  ] = to_tf32(p2);
            Ps[(R0+g+8)*PSS + cb+1] = to_tf32(p3);
        }
        ls0 += __shfl_xor_sync(0xffffffffu, ls0, 1);
        ls0 += __shfl_xor_sync(0xffffffffu, ls0, 2);
        ls1 += __shfl_xor_sync(0xffffffffu, ls1, 1);
        ls1 += __shfl_xor_sync(0xffffffffu, ls1, 2);
        l0v = l0v*al0 + ls0;
        l1v = l1v*al1 + ls1;
        #pragma unroll
        for (int nt = 0; nt < 8; nt++) {
            oc[nt][0] *= al0; oc[nt][1] *= al0;
            oc[nt][2] *= al1; oc[nt][3] *= al1;
        }
        __syncwarp();

        // ---- O += P V ----
        #pragma unroll
        for (int kk = 0; kk < 8; kk++) {
            int kb = kk*8;
            uint32_t a0 = __float_as_uint(Ps[(R0+g  )*PSS + kb+tig]);
            uint32_t a1 = __float_as_uint(Ps[(R0+g+8)*PSS + kb+tig]);
            uint32_t a2 = __float_as_uint(Ps[(R0+g  )*PSS + kb+tig+4]);
            uint32_t a3 = __float_as_uint(Ps[(R0+g+8)*PSS + kb+tig+4]);
            #pragma unroll
            for (int nt = 0; nt < 8; nt++) {
                uint32_t b0 = __float_as_uint(Vb[(kb+tig  )*VS + nt*8+g]);
                uint32_t b1 = __float_as_uint(Vb[(kb+tig+4)*VS + nt*8+g]);
                mma_tf32(oc[nt], a0, a1, a2, a3, b0, b1);
            }
        }
        __syncthreads();
        if (c + 2 < 16) attn_stage(Kc, Vc, Bc, bsrc, h, c + 2, t);
    }

    // epilogue: normalize + gate
    float inv0 = 1.f/l0v, inv1 = 1.f/l1v;
    const float* gg0 = g_g + (size_t)(i0+R0+g    )*INNER + h*DH;
    const float* gg1 = g_g + (size_t)(i0+R0+g + 8)*INNER + h*DH;
    #pragma unroll
    for (int nt = 0; nt < 8; nt++) {
        int cb = nt*8 + tig*2;
        float2 gv0 = *(const float2*)(gg0 + cb);
        float2 gv1 = *(const float2*)(gg1 + cb);
        float s00 = 1.f/(1.f + __expf(-gv0.x));
        float s01 = 1.f/(1.f + __expf(-gv0.y));
        float s10 = 1.f/(1.f + __expf(-gv1.x));
        float s11 = 1.f/(1.f + __expf(-gv1.y));
        *(float2*)(g_attnout + (size_t)(i0+R0+g  )*INNER + h*DH + cb) =
            make_float2(oc[nt][0]*inv0*s00, oc[nt][1]*inv0*s01);
        *(float2*)(g_attnout + (size_t)(i0+R0+g+8)*INNER + h*DH + cb) =
            make_float2(oc[nt][2]*inv1*s10, oc[nt][3]*inv1*s11);
    }
}

// ---------------- outproj v2: BM=32 BN=64 BK=32, cp.async 2-stage ----------------
#define OA_S 36
#define OB_S 72
__global__ __launch_bounds__(256) void outproj2_kernel(
    const float* __restrict__ A, const float* __restrict__ B, float* __restrict__ C)
{
    __shared__ __align__(16) float As[2][32*OA_S];
    __shared__ __align__(16) float Bs[2][32*OB_S];

    const int t = threadIdx.x;
    const int m0 = blockIdx.y * 32;
    const int n0 = blockIdx.x * 64;
    const int wid = t >> 5, lane = t & 31;
    const int wm = wid & 1, wn = wid >> 1;
    const int g = lane >> 2, tig = lane & 3;
    const int R0 = wm * 16, C0 = wn * 16;

    float c[2][4];
    #pragma unroll
    for (int nt = 0; nt < 2; nt++)
        #pragma unroll
        for (int j = 0; j < 4; j++) c[nt][j] = 0.f;

    const int ar = t >> 3, ac4 = (t & 7) * 4;
    const int br = t >> 4, bc4 = (t & 15) * 4;

    #pragma unroll
    for (int s = 0; s < 2; s++) {
        cp16(&As[s][ar*OA_S + ac4], A + (size_t)(m0+ar)*INNER + s*32 + ac4);
        #pragma unroll
        for (int i = 0; i < 2; i++) {
            int row = br + i*16;
            cp16(&Bs[s][row*OB_S + bc4], B + (size_t)(s*32+row)*DS + n0 + bc4);
        }
        CP_COMMIT();
    }

    for (int cc = 0; cc < 32; cc++) {
        if (cc < 31) asm volatile("cp.async.wait_group 1;");
        else         asm volatile("cp.async.wait_group 0;");
        __syncthreads();
        const float* Ab = As[cc & 1];
        const float* Bb = Bs[cc & 1];

        #pragma unroll
        for (int kk = 0; kk < 4; kk++) {
            int kb = kk*8;
            uint32_t a0 = __float_as_uint(to_tf32(Ab[(R0+g  )*OA_S + kb+tig]));
            uint32_t a1 = __float_as_uint(to_tf32(Ab[(R0+g+8)*OA_S + kb+tig]));
            uint32_t a2 = __float_as_uint(to_tf32(Ab[(R0+g  )*OA_S + kb+tig+4]));
            uint32_t a3 = __float_as_uint(to_tf32(Ab[(R0+g+8)*OA_S + kb+tig+4]));
            #pragma unroll
            for (int nt = 0; nt < 2; nt++) {
                uint32_t b0 = __float_as_uint(to_tf32(Bb[(kb+tig  )*OB_S + C0 + nt*8 + g]));
                uint32_t b1 = __float_as_uint(to_tf32(Bb[(kb+tig+4)*OB_S + C0 + nt*8 + g]));
                mma_tf32(c[nt], a0, a1, a2, a3, b0, b1);
            }
        }
        __syncthreads();
        if (cc + 2 < 32) {
            int s = cc & 1, k0 = (cc+2)*32;
            cp16(&As[s][ar*OA_S + ac4], A + (size_t)(m0+ar)*INNER + k0 + ac4);
            #pragma unroll
            for (int i = 0; i < 2; i++) {
                int row = br + i*16;
                cp16(&Bs[s][row*OB_S + bc4], B + (size_t)(k0+row)*DS + n0 + bc4);
            }
            CP_COMMIT();
        }
    }

    #pragma unroll
    for (int nt = 0; nt < 2; nt++) {
        int n = n0 + C0 + nt*8 + tig*2;
        int r0 = m0 + R0 + g;
        *(float2*)(C + (size_t)r0*DS + n)     = make_float2(c[nt][0], c[nt][1]);
        *(float2*)(C + (size_t)(r0+8)*DS + n) = make_float2(c[nt][2], c[nt][3]);
    }
}

// ---------------- launcher ----------------
extern "C" void kernel_launch(void* const* d_in, const int* in_sizes, int n_in,
                              void* d_out, int out_size)
{
    const float* x     = (const float*)d_in[0];
    const float* pw    = (const float*)d_in[1];
    const float* ab    = (const float*)d_in[2];
    const float* gamma = (const float*)d_in[3];
    const float* beta  = (const float*)d_in[4];
    const float* Wb    = (const float*)d_in[5];
    const float* Wq    = (const float*)d_in[6];
    const float* bq    = (const float*)d_in[7];
    const float* Wk    = (const float*)d_in[8];
    const float* Wv    = (const float*)d_in[9];
    const float* Wg    = (const float*)d_in[10];
    const float* Wo    = (const float*)d_in[11];
    float* out = (float*)d_out;

    float* dao; cudaGetSymbolAddress((void**)&dao, g_attnout);

    prep_kernel<<<1, 256>>>(gamma, beta, Wb);

    const int pb_smem = (128*WS_S + 3*128*T_S) * 4;   // 67584
    cudaFuncSetAttribute(fused_pb_kernel, cudaFuncAttributeMaxDynamicSharedMemorySize, pb_smem);
    fused_pb_kernel<<<1024 + NN/128, 256, pb_smem>>>(x, Wq, bq, Wk, Wv, Wg, pw, ab);

    const int attn_smem = (2*64*KS + 2*64*VS + 2*128*BBS + 128*PSS) * 4;  // 176128
    cudaFuncSetAttribute(attn3_kernel, cudaFuncAttributeMaxDynamicSharedMemorySize, attn_smem);
    attn3_kernel<<<dim3(NTOK/128, NH), 256, attn_smem>>>();

    outproj2_kernel<<<dim3(DS/64, NTOK/32), 256>>>(dao, Wo, out);
}

// round 14
// speedup vs baseline: 1.6888x; 1.6888x over previous
#include <cuda_runtime.h>
#include <cstdint>

#define NTOK  1024
#define DS    384
#define DP    128
#define NH    16
#define DH    64
#define INNER 1024
#define NN    (NTOK*NTOK)

// ---------------- scratch ----------------
__device__ float g_q[NTOK*INNER];           // tf32-rounded
__device__ float g_k[NTOK*INNER];           // tf32-rounded
__device__ float g_v[NTOK*INNER];           // tf32-rounded
__device__ float g_g[NTOK*INNER];           // full fp32 (gate)
__device__ float g_scores[(size_t)NH*NN];
__device__ float g_attnout[NTOK*INNER];     // attnout * sigmoid(gate)
__device__ float g_gw[NH*DP];
__device__ float g_T[NH];
__device__ float g_U[NH];

__device__ __forceinline__ float to_tf32(float x) {
    float y;
    asm("cvt.rna.tf32.f32 %0, %1;" : "=f"(y) : "f"(x));
    return y;
}
__device__ __forceinline__ void mma_tf32(float c[4],
    uint32_t a0, uint32_t a1, uint32_t a2, uint32_t a3,
    uint32_t b0, uint32_t b1)
{
    asm volatile("mma.sync.aligned.m16n8k8.row.col.f32.tf32.tf32.f32 "
        "{%0,%1,%2,%3}, {%4,%5,%6,%7}, {%8,%9}, {%0,%1,%2,%3};"
        : "+f"(c[0]), "+f"(c[1]), "+f"(c[2]), "+f"(c[3])
        : "r"(a0), "r"(a1), "r"(a2), "r"(a3), "r"(b0), "r"(b1));
}
__device__ __forceinline__ void cp16(float* dst, const float* src) {
    uint32_t s = (uint32_t)__cvta_generic_to_shared(dst);
    asm volatile("cp.async.cg.shared.global [%0], [%1], 16;" :: "r"(s), "l"(src));
}
#define CP_COMMIT() asm volatile("cp.async.commit_group;")

// ---------------- K0: tiny precompute ----------------
__global__ void prep_kernel(const float* __restrict__ gamma,
                            const float* __restrict__ beta,
                            const float* __restrict__ Wb)
{
    int t = threadIdx.x;
    for (int l = t; l < NH*DP; l += blockDim.x) {
        int h = l / DP, d = l % DP;
        g_gw[h*DP + d] = gamma[d] * Wb[d*NH + h];
    }
    if (t < 2*NH) {
        int h = t % NH;
        const float* src = (t < NH) ? gamma : beta;
        float s = 0.f;
        for (int d = 0; d < DP; d++) s += src[d] * Wb[d*NH + h];
        if (t < NH) g_T[h] = s; else g_U[h] = s;
    }
}

// ---------------- fused proj(4x) + bias kernel ----------------
#define AS_S 20
#define BS_S 72
#define WS_S 24
#define T_S  36

__device__ __forceinline__ void proj_body(float* smem,
    const float* __restrict__ X, const float* __restrict__ B,
    const float* __restrict__ bq, int sel, int bx, int by)
{
    float* As = smem;
    float* Bs = smem + 64*AS_S;
    float* C = (sel==0) ? g_q : (sel==1) ? g_k : (sel==2) ? g_v : g_g;

    const int t = threadIdx.x;
    const int m0 = by * 64;
    const int n0 = bx * 64;
    const int wid = t >> 5, lane = t & 31;
    const int wm = wid & 1, wn = wid >> 1;
    const int g = lane >> 2, tig = lane & 3;
    const int R0 = wm * 32, C0 = wn * 16;

    float c[2][2][4];
    #pragma unroll
    for (int mt = 0; mt < 2; mt++)
        #pragma unroll
        for (int nt = 0; nt < 2; nt++)
            #pragma unroll
            for (int j = 0; j < 4; j++) c[mt][nt][j] = 0.f;

    const int am = t >> 2, akq = (t & 3) * 4;
    const int bk = t >> 4, bn4 = (t & 15) * 4;

    for (int k0 = 0; k0 < DS; k0 += 16) {
        {
            float4 av = *(const float4*)(X + (size_t)(m0+am)*DS + k0 + akq);
            float* d = As + am*AS_S + akq;
            d[0]=to_tf32(av.x); d[1]=to_tf32(av.y); d[2]=to_tf32(av.z); d[3]=to_tf32(av.w);
        }
        {
            float4 bv = *(const float4*)(B + (size_t)(k0+bk)*INNER + n0 + bn4);
            float* d = Bs + bk*BS_S + bn4;
            d[0]=to_tf32(bv.x); d[1]=to_tf32(bv.y); d[2]=to_tf32(bv.z); d[3]=to_tf32(bv.w);
        }
        __syncthreads();
        #pragma unroll
        for (int kk = 0; kk < 2; kk++) {
            int kb = kk * 8;
            uint32_t b0[2], b1[2];
            #pragma unroll
            for (int nt = 0; nt < 2; nt++) {
                b0[nt] = __float_as_uint(Bs[(kb+tig  )*BS_S + C0 + nt*8 + g]);
                b1[nt] = __float_as_uint(Bs[(kb+tig+4)*BS_S + C0 + nt*8 + g]);
            }
            #pragma unroll
            for (int mt = 0; mt < 2; mt++) {
                uint32_t a0 = __float_as_uint(As[(R0+mt*16+g  )*AS_S + kb+tig]);
                uint32_t a1 = __float_as_uint(As[(R0+mt*16+g+8)*AS_S + kb+tig]);
                uint32_t a2 = __float_as_uint(As[(R0+mt*16+g  )*AS_S + kb+tig+4]);
                uint32_t a3 = __float_as_uint(As[(R0+mt*16+g+8)*AS_S + kb+tig+4]);
                #pragma unroll
                for (int nt = 0; nt < 2; nt++)
                    mma_tf32(c[mt][nt], a0, a1, a2, a3, b0[nt], b1[nt]);
            }
        }
        __syncthreads();
    }

    #pragma unroll
    for (int mt = 0; mt < 2; mt++) {
        #pragma unroll
        for (int nt = 0; nt < 2; nt++) {
            int n = n0 + C0 + nt*8 + tig*2;
            float bx2 = 0.f, by2 = 0.f;
            if (sel == 0) { bx2 = bq[n]; by2 = bq[n+1]; }
            int r0 = m0 + R0 + mt*16 + g;
            float v00 = c[mt][nt][0]+bx2, v01 = c[mt][nt][1]+by2;
            float v10 = c[mt][nt][2]+bx2, v11 = c[mt][nt][3]+by2;
            if (sel < 3) {   // q,k,v pre-rounded to tf32 (idempotent vs consumer-side round)
                v00 = to_tf32(v00); v01 = to_tf32(v01);
                v10 = to_tf32(v10); v11 = to_tf32(v11);
            }
            *(float2*)(C + (size_t)r0*INNER + n)     = make_float2(v00, v01);
            *(float2*)(C + (size_t)(r0+8)*INNER + n) = make_float2(v10, v11);
        }
    }
}

// ---- bias body: R6 depth-2 version (4 CTAs/SM) ----
__device__ __forceinline__ void bias_body(float* smem,
    const float* __restrict__ pw, const float* __restrict__ ab, int bid)
{
    float* Ws = smem;
    float* T  = smem + 128*WS_S;

    const int t = threadIdx.x;
    const size_t pb = (size_t)bid * 128;
    const int srow = t >> 3, sc4 = (t & 7) * 4;

    #pragma unroll
    for (int i = 0; i < 4; i++) {
        int row = srow + i*32;
        cp16(&T[row*T_S + sc4], pw + (pb+row)*DP + sc4);
    }
    CP_COMMIT();

    for (int l = t; l < 16*128; l += 256) {
        int h = l >> 7, d = l & 127;
        Ws[d*WS_S + h] = to_tf32(g_gw[h*DP + d]);
    }

    #pragma unroll
    for (int i = 0; i < 4; i++) {
        int row = srow + i*32;
        cp16(&T[128*T_S + row*T_S + sc4], pw + (pb+row)*DP + 32 + sc4);
    }
    CP_COMMIT();

    const int wid = t >> 5, lane = t & 31;
    const int g = lane >> 2, tig = lane & 3;
    const int r0 = wid*16 + g;

    float c[2][4];
    #pragma unroll
    for (int nt = 0; nt < 2; nt++)
        #pragma unroll
        for (int j = 0; j < 4; j++) c[nt][j] = 0.f;
    float s0 = 0.f, q0 = 0.f, s1 = 0.f, q1 = 0.f;

    for (int cc = 0; cc < 4; cc++) {
        if (cc < 3) asm volatile("cp.async.wait_group 1;");
        else        asm volatile("cp.async.wait_group 0;");
        __syncthreads();
        float* Tb = T + (cc & 1) * 128*T_S;

        #pragma unroll
        for (int ks = 0; ks < 4; ks++) {
            int kb = ks*8;
            float a0 = Tb[(r0  )*T_S + kb+tig];
            float a1 = Tb[(r0+8)*T_S + kb+tig];
            float a2 = Tb[(r0  )*T_S + kb+tig+4];
            float a3 = Tb[(r0+8)*T_S + kb+tig+4];
            s0 += a0 + a2;  q0 += a0*a0 + a2*a2;
            s1 += a1 + a3;  q1 += a1*a1 + a3*a3;
            uint32_t u0 = __float_as_uint(to_tf32(a0));
            uint32_t u1 = __float_as_uint(to_tf32(a1));
            uint32_t u2 = __float_as_uint(to_tf32(a2));
            uint32_t u3 = __float_as_uint(to_tf32(a3));
            int kg = cc*32 + kb;
            #pragma unroll
            for (int nt = 0; nt < 2; nt++) {
                uint32_t b0 = __float_as_uint(Ws[(kg+tig  )*WS_S + nt*8 + g]);
                uint32_t b1 = __float_as_uint(Ws[(kg+tig+4)*WS_S + nt*8 + g]);
                mma_tf32(c[nt], u0, u1, u2, u3, b0, b1);
            }
        }
        __syncthreads();
        if (cc + 2 < 4) {
            #pragma unroll
            for (int i = 0; i < 4; i++) {
                int row = srow + i*32;
                cp16(&T[(cc&1)*128*T_S + row*T_S + sc4], pw + (pb+row)*DP + (cc+2)*32 + sc4);
            }
            CP_COMMIT();
        }
    }

    s0 += __shfl_xor_sync(0xffffffffu, s0, 1); s0 += __shfl_xor_sync(0xffffffffu, s0, 2);
    q0 += __shfl_xor_sync(0xffffffffu, q0, 1); q0 += __shfl_xor_sync(0xffffffffu, q0, 2);
    s1 += __shfl_xor_sync(0xffffffffu, s1, 1); s1 += __shfl_xor_sync(0xffffffffu, s1, 2);
    q1 += __shfl_xor_sync(0xffffffffu, q1, 1); q1 += __shfl_xor_sync(0xffffffffu, q1, 2);

    float mu0 = s0 * (1.f/DP), mu1 = s1 * (1.f/DP);
    float rinv0 = rsqrtf(q0*(1.f/DP) - mu0*mu0 + 1e-5f);
    float rinv1 = rsqrtf(q1*(1.f/DP) - mu1*mu1 + 1e-5f);
    float ab0 = ab[pb + r0], ab1 = ab[pb + r0 + 8];

    float* Ss = T;
    #pragma unroll
    for (int nt = 0; nt < 2; nt++) {
        #pragma unroll
        for (int j = 0; j < 2; j++) {
            int h = nt*8 + tig*2 + j;
            float Th = g_T[h], Uh = g_U[h];
            Ss[(r0    )*17 + h] = rinv0*(c[nt][j  ] - mu0*Th) + Uh + ab0;
            Ss[(r0 + 8)*17 + h] = rinv1*(c[nt][2+j] - mu1*Th) + Uh + ab1;
        }
    }
    __syncthreads();
    for (int l = t; l < 2048; l += 256) {
        int h = l >> 7, r = l & 127;
        g_scores[(size_t)h*NN + pb + r] = Ss[r*17 + h];
    }
}

__global__ __launch_bounds__(256) void fused_pb_kernel(
    const float* __restrict__ X,
    const float* __restrict__ Wq, const float* __restrict__ bq,
    const float* __restrict__ Wk, const float* __restrict__ Wv,
    const float* __restrict__ Wg,
    const float* __restrict__ pw, const float* __restrict__ ab)
{
    extern __shared__ float smem[];
    int bid = blockIdx.x;
    if (bid < 1024) {
        int sel = bid >> 8;
        int rem = bid & 255;
        const float* B = (sel==0) ? Wq : (sel==1) ? Wk : (sel==2) ? Wv : Wg;
        proj_body(smem, X, B, bq, sel, rem & 15, rem >> 4);
    } else {
        bias_body(smem, pw, ab, bid - 1024);
    }
}

// ---------------- attn v4: cp.async double-buffered, COALESCED patterns ----------------
#define KS  68
#define VS  72
#define BBS 68
#define PSS 68

__device__ __forceinline__ void attn_stage(float* Kc, float* Vc, float* Bc,
    const float* bsrc, int h, int c, int t)
{
    const int buf = c & 1;
    const int jc = c * 64;
    float* Kb = Kc + buf*64*KS;
    float* Vb = Vc + buf*64*VS;
    float* Bb = Bc + buf*128*BBS;
    // K/V: per-instruction contiguous (warp covers 2 rows x 64 cols)
    #pragma unroll
    for (int i = 0; i < 4; i++) {
        int l = t*4 + i*1024;
        int r = l >> 6, d = l & 63;
        cp16(Kb + r*KS + d, g_k + (size_t)(jc+r)*INNER + h*DH + d);
        cp16(Vb + r*VS + d, g_v + (size_t)(jc+r)*INNER + h*DH + d);
    }
    // bias: per-instruction contiguous (warp covers 2 rows x 64 cols)
    const int br = t >> 4, bc4 = (t & 15) * 4;
    const float* bs = bsrc + jc;
    #pragma unroll
    for (int j = 0; j < 8; j++) {
        int row = br + j*16;
        cp16(Bb + row*BBS + bc4, bs + (size_t)row*NTOK + bc4);
    }
    CP_COMMIT();
}

__global__ __launch_bounds__(256, 1) void attn4_kernel()
{
    extern __shared__ float sm2[];
    float* Kc = sm2;                    // 2 * 64*KS
    float* Vc = Kc + 2*64*KS;           // 2 * 64*VS
    float* Bc = Vc + 2*64*VS;           // 2 * 128*BBS
    float* Ps = Bc + 2*128*BBS;         // 128*PSS

    const int t = threadIdx.x;
    const int h = blockIdx.y;
    const int i0 = blockIdx.x * 128;
    const int wid = t >> 5, lane = t & 31;
    const int g = lane >> 2, tig = lane & 3;
    const int R0 = wid * 16;
    const float* bsrc = g_scores + (size_t)h * NN + (size_t)i0 * NTOK;

    attn_stage(Kc, Vc, Bc, bsrc, h, 0, t);

    // Q fragments (g_q pre-rounded tf32)
    uint32_t qf[8][4];
    {
        const float* q0 = g_q + (size_t)(i0 + R0 + g    ) * INNER + h*DH;
        const float* q1 = g_q + (size_t)(i0 + R0 + g + 8) * INNER + h*DH;
        #pragma unroll
        for (int kk = 0; kk < 8; kk++) {
            qf[kk][0] = __float_as_uint(q0[kk*8 + tig]);
            qf[kk][1] = __float_as_uint(q1[kk*8 + tig]);
            qf[kk][2] = __float_as_uint(q0[kk*8 + tig + 4]);
            qf[kk][3] = __float_as_uint(q1[kk*8 + tig + 4]);
        }
    }

    attn_stage(Kc, Vc, Bc, bsrc, h, 1, t);

    float oc[8][4];
    #pragma unroll
    for (int nt = 0; nt < 8; nt++)
        #pragma unroll
        for (int j = 0; j < 4; j++) oc[nt][j] = 0.f;
    float m0v = -1e30f, m1v = -1e30f, l0v = 0.f, l1v = 0.f;

    for (int c = 0; c < 16; c++) {
        if (c < 15) asm volatile("cp.async.wait_group 1;");
        else        asm volatile("cp.async.wait_group 0;");
        __syncthreads();
        const float* Kb = Kc + (c&1)*64*KS;
        const float* Vb = Vc + (c&1)*64*VS;
        const float* Bcur = Bc + (c&1)*128*BBS;

        // ---- S = Q K^T ----
        float sc[8][4];
        #pragma unroll
        for (int nt = 0; nt < 8; nt++)
            #pragma unroll
            for (int j = 0; j < 4; j++) sc[nt][j] = 0.f;
        #pragma unroll
        for (int kk = 0; kk < 8; kk++) {
            #pragma unroll
            for (int nt = 0; nt < 8; nt++) {
                uint32_t b0 = __float_as_uint(Kb[(nt*8+g)*KS + kk*8+tig]);
                uint32_t b1 = __float_as_uint(Kb[(nt*8+g)*KS + kk*8+tig+4]);
                mma_tf32(sc[nt], qf[kk][0], qf[kk][1], qf[kk][2], qf[kk][3], b0, b1);
            }
        }

        // ---- scale + bias + warp-local row max ----
        float rm0 = -1e30f, rm1 = -1e30f;
        #pragma unroll
        for (int nt = 0; nt < 8; nt++) {
            int cb = nt*8 + tig*2;
            sc[nt][0] = sc[nt][0]*0.125f + Bcur[(R0+g  )*BBS + cb];
            sc[nt][1] = sc[nt][1]*0.125f + Bcur[(R0+g  )*BBS + cb+1];
            sc[nt][2] = sc[nt][2]*0.125f + Bcur[(R0+g+8)*BBS + cb];
            sc[nt][3] = sc[nt][3]*0.125f + Bcur[(R0+g+8)*BBS + cb+1];
            rm0 = fmaxf(rm0, fmaxf(sc[nt][0], sc[nt][1]));
            rm1 = fmaxf(rm1, fmaxf(sc[nt][2], sc[nt][3]));
        }
        rm0 = fmaxf(rm0, __shfl_xor_sync(0xffffffffu, rm0, 1));
        rm0 = fmaxf(rm0, __shfl_xor_sync(0xffffffffu, rm0, 2));
        rm1 = fmaxf(rm1, __shfl_xor_sync(0xffffffffu, rm1, 1));
        rm1 = fmaxf(rm1, __shfl_xor_sync(0xffffffffu, rm1, 2));

        float mn0 = fmaxf(m0v, rm0), mn1 = fmaxf(m1v, rm1);
        float al0 = __expf(m0v - mn0), al1 = __expf(m1v - mn1);
        m0v = mn0; m1v = mn1;

        float ls0 = 0.f, ls1 = 0.f;
        #pragma unroll
        for (int nt = 0; nt < 8; nt++) {
            int cb = nt*8 + tig*2;
            float p0 = __expf(sc[nt][0] - mn0);
            float p1 = __expf(sc[nt][1] - mn0);
            float p2 = __expf(sc[nt][2] - mn1);
            float p3 = __expf(sc[nt][3] - mn1);
            ls0 += p0 + p1; ls1 += p2 + p3;
            Ps[(R0+g  )*PSS + cb  ] = to_tf32(p0);
            Ps[(R0+g  )*PSS + cb+1] = to_tf32(p1);
            Ps[(R0+g+8)*PSS + cb  ] = to_tf32(p2);
            Ps[(R0+g+8)*PSS + cb+1] = to_tf32(p3);
        }
        ls0 += __shfl_xor_sync(0xffffffffu, ls0, 1);
        ls0 += __shfl_xor_sync(0xffffffffu, ls0, 2);
        ls1 += __shfl_xor_sync(0xffffffffu, ls1, 1);
        ls1 += __shfl_xor_sync(0xffffffffu, ls1, 2);
        l0v = l0v*al0 + ls0;
        l1v = l1v*al1 + ls1;
        #pragma unroll
        for (int nt = 0; nt < 8; nt++) {
            oc[nt][0] *= al0; oc[nt][1] *= al0;
            oc[nt][2] *= al1; oc[nt][3] *= al1;
        }
        __syncwarp();

        // ---- O += P V ----
        #pragma unroll
        for (int kk = 0; kk < 8; kk++) {
            int kb = kk*8;
            uint32_t a0 = __float_as_uint(Ps[(R0+g  )*PSS + kb+tig]);
            uint32_t a1 = __float_as_uint(Ps[(R0+g+8)*PSS + kb+tig]);
            uint32_t a2 = __float_as_uint(Ps[(R0+g  )*PSS + kb+tig+4]);
            uint32_t a3 = __float_as_uint(Ps[(R0+g+8)*PSS + kb+tig+4]);
            #pragma unroll
            for (int nt = 0; nt < 8; nt++) {
                uint32_t b0 = __float_as_uint(Vb[(kb+tig  )*VS + nt*8+g]);
                uint32_t b1 = __float_as_uint(Vb[(kb+tig+4)*VS + nt*8+g]);
                mma_tf32(oc[nt], a0, a1, a2, a3, b0, b1);
            }
        }
        __syncthreads();
        if (c + 2 < 16) attn_stage(Kc, Vc, Bc, bsrc, h, c + 2, t);
    }

    // epilogue: normalize + gate
    float inv0 = 1.f/l0v, inv1 = 1.f/l1v;
    const float* gg0 = g_g + (size_t)(i0+R0+g    )*INNER + h*DH;
    const float* gg1 = g_g + (size_t)(i0+R0+g + 8)*INNER + h*DH;
    #pragma unroll
    for (int nt = 0; nt < 8; nt++) {
        int cb = nt*8 + tig*2;
        float2 gv0 = *(const float2*)(gg0 + cb);
        float2 gv1 = *(const float2*)(gg1 + cb);
        float s00 = 1.f/(1.f + __expf(-gv0.x));
        float s01 = 1.f/(1.f + __expf(-gv0.y));
        float s10 = 1.f/(1.f + __expf(-gv1.x));
        float s11 = 1.f/(1.f + __expf(-gv1.y));
        *(float2*)(g_attnout + (size_t)(i0+R0+g  )*INNER + h*DH + cb) =
            make_float2(oc[nt][0]*inv0*s00, oc[nt][1]*inv0*s01);
        *(float2*)(g_attnout + (size_t)(i0+R0+g+8)*INNER + h*DH + cb) =
            make_float2(oc[nt][2]*inv1*s10, oc[nt][3]*inv1*s11);
    }
}

// ---------------- outproj v2: BM=32 BN=64 BK=32, cp.async 2-stage ----------------
#define OA_S 36
#define OB_S 72
__global__ __launch_bounds__(256) void outproj2_kernel(
    const float* __restrict__ A, const float* __restrict__ B, float* __restrict__ C)
{
    __shared__ __align__(16) float As[2][32*OA_S];
    __shared__ __align__(16) float Bs[2][32*OB_S];

    const int t = threadIdx.x;
    const int m0 = blockIdx.y * 32;
    const int n0 = blockIdx.x * 64;
    const int wid = t >> 5, lane = t & 31;
    const int wm = wid & 1, wn = wid >> 1;
    const int g = lane >> 2, tig = lane & 3;
    const int R0 = wm * 16, C0 = wn * 16;

    float c[2][4];
    #pragma unroll
    for (int nt = 0; nt < 2; nt++)
        #pragma unroll
        for (int j = 0; j < 4; j++) c[nt][j] = 0.f;

    const int ar = t >> 3, ac4 = (t & 7) * 4;
    const int br = t >> 4, bc4 = (t & 15) * 4;

    #pragma unroll
    for (int s = 0; s < 2; s++) {
        cp16(&As[s][ar*OA_S + ac4], A + (size_t)(m0+ar)*INNER + s*32 + ac4);
        #pragma unroll
        for (int i = 0; i < 2; i++) {
            int row = br + i*16;
            cp16(&Bs[s][row*OB_S + bc4], B + (size_t)(s*32+row)*DS + n0 + bc4);
        }
        CP_COMMIT();
    }

    for (int cc = 0; cc < 32; cc++) {
        if (cc < 31) asm volatile("cp.async.wait_group 1;");
        else         asm volatile("cp.async.wait_group 0;");
        __syncthreads();
        const float* Ab = As[cc & 1];
        const float* Bb = Bs[cc & 1];

        #pragma unroll
        for (int kk = 0; kk < 4; kk++) {
            int kb = kk*8;
            uint32_t a0 = __float_as_uint(to_tf32(Ab[(R0+g  )*OA_S + kb+tig]));
            uint32_t a1 = __float_as_uint(to_tf32(Ab[(R0+g+8)*OA_S + kb+tig]));
            uint32_t a2 = __float_as_uint(to_tf32(Ab[(R0+g  )*OA_S + kb+tig+4]));
            uint32_t a3 = __float_as_uint(to_tf32(Ab[(R0+g+8)*OA_S + kb+tig+4]));
            #pragma unroll
            for (int nt = 0; nt < 2; nt++) {
                uint32_t b0 = __float_as_uint(to_tf32(Bb[(kb+tig  )*OB_S + C0 + nt*8 + g]));
                uint32_t b1 = __float_as_uint(to_tf32(Bb[(kb+tig+4)*OB_S + C0 + nt*8 + g]));
                mma_tf32(c[nt], a0, a1, a2, a3, b0, b1);
            }
        }
        __syncthreads();
        if (cc + 2 < 32) {
            int s = cc & 1, k0 = (cc+2)*32;
            cp16(&As[s][ar*OA_S + ac4], A + (size_t)(m0+ar)*INNER + k0 + ac4);
            #pragma unroll
            for (int i = 0; i < 2; i++) {
                int row = br + i*16;
                cp16(&Bs[s][row*OB_S + bc4], B + (size_t)(k0+row)*DS + n0 + bc4);
            }
            CP_COMMIT();
        }
    }

    #pragma unroll
    for (int nt = 0; nt < 2; nt++) {
        int n = n0 + C0 + nt*8 + tig*2;
        int r0 = m0 + R0 + g;
        *(float2*)(C + (size_t)r0*DS + n)     = make_float2(c[nt][0], c[nt][1]);
        *(float2*)(C + (size_t)(r0+8)*DS + n) = make_float2(c[nt][2], c[nt][3]);
    }
}

// ---------------- launcher ----------------
extern "C" void kernel_launch(void* const* d_in, const int* in_sizes, int n_in,
                              void* d_out, int out_size)
{
    const float* x     = (const float*)d_in[0];
    const float* pw    = (const float*)d_in[1];
    const float* ab    = (const float*)d_in[2];
    const float* gamma = (const float*)d_in[3];
    const float* beta  = (const float*)d_in[4];
    const float* Wb    = (const float*)d_in[5];
    const float* Wq    = (const float*)d_in[6];
    const float* bq    = (const float*)d_in[7];
    const float* Wk    = (const float*)d_in[8];
    const float* Wv    = (const float*)d_in[9];
    const float* Wg    = (const float*)d_in[10];
    const float* Wo    = (const float*)d_in[11];
    float* out = (float*)d_out;

    float* dao; cudaGetSymbolAddress((void**)&dao, g_attnout);

    prep_kernel<<<1, 256>>>(gamma, beta, Wb);

    const int pb_smem = (128*WS_S + 2*128*T_S) * 4;   // 49152 -> 4 CTAs/SM
    cudaFuncSetAttribute(fused_pb_kernel, cudaFuncAttributeMaxDynamicSharedMemorySize, pb_smem);
    fused_pb_kernel<<<1024 + NN/128, 256, pb_smem>>>(x, Wq, bq, Wk, Wv, Wg, pw, ab);

    const int attn_smem = (2*64*KS + 2*64*VS + 2*128*BBS + 128*PSS) * 4;  // 176128
    cudaFuncSetAttribute(attn4_kernel, cudaFuncAttributeMaxDynamicSharedMemorySize, attn_smem);
    attn4_kernel<<<dim3(NTOK/128, NH), 256, attn_smem>>>();

    outproj2_kernel<<<dim3(DS/64, NTOK/32), 256>>>(dao, Wo, out);
}

// round 17
// speedup vs baseline: 1.7922x; 1.0612x over previous
#include <cuda_runtime.h>
#include <cstdint>

#define NTOK  1024
#define DS    384
#define DP    128
#define NH    16
#define DH    64
#define INNER 1024
#define NN    (NTOK*NTOK)

// ---------------- scratch ----------------
__device__ float g_q[NTOK*INNER];           // tf32-rounded
__device__ float g_k[NTOK*INNER];           // tf32-rounded
__device__ float g_v[NTOK*INNER];           // tf32-rounded
__device__ float g_g[NTOK*INNER];           // full fp32 (gate)
__device__ float g_scores[(size_t)NH*NN];
__device__ float g_attnout[NTOK*INNER];     // attnout * sigmoid(gate)
__device__ float g_gw[NH*DP];
__device__ float g_T[NH];
__device__ float g_U[NH];

__device__ __forceinline__ float to_tf32(float x) {
    float y;
    asm("cvt.rna.tf32.f32 %0, %1;" : "=f"(y) : "f"(x));
    return y;
}
__device__ __forceinline__ void mma_tf32(float c[4],
    uint32_t a0, uint32_t a1, uint32_t a2, uint32_t a3,
    uint32_t b0, uint32_t b1)
{
    asm volatile("mma.sync.aligned.m16n8k8.row.col.f32.tf32.tf32.f32 "
        "{%0,%1,%2,%3}, {%4,%5,%6,%7}, {%8,%9}, {%0,%1,%2,%3};"
        : "+f"(c[0]), "+f"(c[1]), "+f"(c[2]), "+f"(c[3])
        : "r"(a0), "r"(a1), "r"(a2), "r"(a3), "r"(b0), "r"(b1));
}
__device__ __forceinline__ void cp16(float* dst, const float* src) {
    uint32_t s = (uint32_t)__cvta_generic_to_shared(dst);
    asm volatile("cp.async.cg.shared.global [%0], [%1], 16;" :: "r"(s), "l"(src));
}
#define CP_COMMIT() asm volatile("cp.async.commit_group;")

// ---------------- K0: tiny precompute ----------------
__global__ void prep_kernel(const float* __restrict__ gamma,
                            const float* __restrict__ beta,
                            const float* __restrict__ Wb)
{
    int t = threadIdx.x;
    for (int l = t; l < NH*DP; l += blockDim.x) {
        int h = l / DP, d = l % DP;
        g_gw[h*DP + d] = gamma[d] * Wb[d*NH + h];
    }
    if (t < 2*NH) {
        int h = t % NH;
        const float* src = (t < NH) ? gamma : beta;
        float s = 0.f;
        for (int d = 0; d < DP; d++) s += src[d] * Wb[d*NH + h];
        if (t < NH) g_T[h] = s; else g_U[h] = s;
    }
}

// ---------------- fused proj(4x) + bias kernel ----------------
#define WS_S 24
#define T_S  36
#define PA_S 36
#define PB_S 72

// proj v2: BK=32, cp.async 2-stage
__device__ __forceinline__ void proj_body(float* smem,
    const float* __restrict__ X, const float* __restrict__ B,
    const float* __restrict__ bq, int sel, int bx, int by)
{
    float* As = smem;                   // 2 * 64*PA_S
    float* Bs = smem + 2*64*PA_S;       // 2 * 32*PB_S
    float* C = (sel==0) ? g_q : (sel==1) ? g_k : (sel==2) ? g_v : g_g;

    const int t = threadIdx.x;
    const int m0 = by * 64;
    const int n0 = bx * 64;
    const int wid = t >> 5, lane = t & 31;
    const int wm = wid & 1, wn = wid >> 1;
    const int g = lane >> 2, tig = lane & 3;
    const int R0 = wm * 32, C0 = wn * 16;

    const int ar = t >> 3, ac4 = (t & 7) * 4;     // A: 32 rows x 32 cols per pass
    const int br = t >> 4, bc4 = (t & 15) * 4;    // B: 16 rows x 64 cols per pass

    float c[2][2][4];
    #pragma unroll
    for (int mt = 0; mt < 2; mt++)
        #pragma unroll
        for (int nt = 0; nt < 2; nt++)
            #pragma unroll
            for (int j = 0; j < 4; j++) c[mt][nt][j] = 0.f;

    // prologue: stage chunks 0, 1
    #pragma unroll
    for (int s = 0; s < 2; s++) {
        int k0 = s * 32;
        #pragma unroll
        for (int i = 0; i < 2; i++) {
            int row = ar + i*32;
            cp16(&As[s*64*PA_S + row*PA_S + ac4], X + (size_t)(m0+row)*DS + k0 + ac4);
        }
        #pragma unroll
        for (int i = 0; i < 2; i++) {
            int row = br + i*16;
            cp16(&Bs[s*32*PB_S + row*PB_S + bc4], B + (size_t)(k0+row)*INNER + n0 + bc4);
        }
        CP_COMMIT();
    }

    for (int cc = 0; cc < 12; cc++) {          // DS/32 = 12 chunks
        if (cc < 11) asm volatile("cp.async.wait_group 1;");
        else         asm volatile("cp.async.wait_group 0;");
        __syncthreads();
        const float* Ab = As + (cc & 1)*64*PA_S;
        const float* Bb = Bs + (cc & 1)*32*PB_S;

        #pragma unroll
        for (int kk = 0; kk < 4; kk++) {
            int kb = kk * 8;
            uint32_t b0[2], b1[2];
            #pragma unroll
            for (int nt = 0; nt < 2; nt++) {
                b0[nt] = __float_as_uint(to_tf32(Bb[(kb+tig  )*PB_S + C0 + nt*8 + g]));
                b1[nt] = __float_as_uint(to_tf32(Bb[(kb+tig+4)*PB_S + C0 + nt*8 + g]));
            }
            #pragma unroll
            for (int mt = 0; mt < 2; mt++) {
                uint32_t a0 = __float_as_uint(to_tf32(Ab[(R0+mt*16+g  )*PA_S + kb+tig]));
                uint32_t a1 = __float_as_uint(to_tf32(Ab[(R0+mt*16+g+8)*PA_S + kb+tig]));
                uint32_t a2 = __float_as_uint(to_tf32(Ab[(R0+mt*16+g  )*PA_S + kb+tig+4]));
                uint32_t a3 = __float_as_uint(to_tf32(Ab[(R0+mt*16+g+8)*PA_S + kb+tig+4]));
                #pragma unroll
                for (int nt = 0; nt < 2; nt++)
                    mma_tf32(c[mt][nt], a0, a1, a2, a3, b0[nt], b1[nt]);
            }
        }
        __syncthreads();
        if (cc + 2 < 12) {
            int s = cc & 1, k0 = (cc+2)*32;
            #pragma unroll
            for (int i = 0; i < 2; i++) {
                int row = ar + i*32;
                cp16(&As[s*64*PA_S + row*PA_S + ac4], X + (size_t)(m0+row)*DS + k0 + ac4);
            }
            #pragma unroll
            for (int i = 0; i < 2; i++) {
                int row = br + i*16;
                cp16(&Bs[s*32*PB_S + row*PB_S + bc4], B + (size_t)(k0+row)*INNER + n0 + bc4);
            }
            CP_COMMIT();
        }
    }

    #pragma unroll
    for (int mt = 0; mt < 2; mt++) {
        #pragma unroll
        for (int nt = 0; nt < 2; nt++) {
            int n = n0 + C0 + nt*8 + tig*2;
            float bx2 = 0.f, by2 = 0.f;
            if (sel == 0) { bx2 = bq[n]; by2 = bq[n+1]; }
            int r0 = m0 + R0 + mt*16 + g;
            float v00 = c[mt][nt][0]+bx2, v01 = c[mt][nt][1]+by2;
            float v10 = c[mt][nt][2]+bx2, v11 = c[mt][nt][3]+by2;
            if (sel < 3) {   // q,k,v pre-rounded to tf32 (idempotent vs consumer-side round)
                v00 = to_tf32(v00); v01 = to_tf32(v01);
                v10 = to_tf32(v10); v11 = to_tf32(v11);
            }
            *(float2*)(C + (size_t)r0*INNER + n)     = make_float2(v00, v01);
            *(float2*)(C + (size_t)(r0+8)*INNER + n) = make_float2(v10, v11);
        }
    }
}

// ---- bias body: depth-2, 4 CTAs/SM (unchanged from R8) ----
__device__ __forceinline__ void bias_body(float* smem,
    const float* __restrict__ pw, const float* __restrict__ ab, int bid)
{
    float* Ws = smem;
    float* T  = smem + 128*WS_S;

    const int t = threadIdx.x;
    const size_t pb = (size_t)bid * 128;
    const int srow = t >> 3, sc4 = (t & 7) * 4;

    #pragma unroll
    for (int i = 0; i < 4; i++) {
        int row = srow + i*32;
        cp16(&T[row*T_S + sc4], pw + (pb+row)*DP + sc4);
    }
    CP_COMMIT();

    for (int l = t; l < 16*128; l += 256) {
        int h = l >> 7, d = l & 127;
        Ws[d*WS_S + h] = to_tf32(g_gw[h*DP + d]);
    }

    #pragma unroll
    for (int i = 0; i < 4; i++) {
        int row = srow + i*32;
        cp16(&T[128*T_S + row*T_S + sc4], pw + (pb+row)*DP + 32 + sc4);
    }
    CP_COMMIT();

    const int wid = t >> 5, lane = t & 31;
    const int g = lane >> 2, tig = lane & 3;
    const int r0 = wid*16 + g;

    float c[2][4];
    #pragma unroll
    for (int nt = 0; nt < 2; nt++)
        #pragma unroll
        for (int j = 0; j < 4; j++) c[nt][j] = 0.f;
    float s0 = 0.f, q0 = 0.f, s1 = 0.f, q1 = 0.f;

    for (int cc = 0; cc < 4; cc++) {
        if (cc < 3) asm volatile("cp.async.wait_group 1;");
        else        asm volatile("cp.async.wait_group 0;");
        __syncthreads();
        float* Tb = T + (cc & 1) * 128*T_S;

        #pragma unroll
        for (int ks = 0; ks < 4; ks++) {
            int kb = ks*8;
            float a0 = Tb[(r0  )*T_S + kb+tig];
            float a1 = Tb[(r0+8)*T_S + kb+tig];
            float a2 = Tb[(r0  )*T_S + kb+tig+4];
            float a3 = Tb[(r0+8)*T_S + kb+tig+4];
            s0 += a0 + a2;  q0 += a0*a0 + a2*a2;
            s1 += a1 + a3;  q1 += a1*a1 + a3*a3;
            uint32_t u0 = __float_as_uint(to_tf32(a0));
            uint32_t u1 = __float_as_uint(to_tf32(a1));
            uint32_t u2 = __float_as_uint(to_tf32(a2));
            uint32_t u3 = __float_as_uint(to_tf32(a3));
            int kg = cc*32 + kb;
            #pragma unroll
            for (int nt = 0; nt < 2; nt++) {
                uint32_t b0 = __float_as_uint(Ws[(kg+tig  )*WS_S + nt*8 + g]);
                uint32_t b1 = __float_as_uint(Ws[(kg+tig+4)*WS_S + nt*8 + g]);
                mma_tf32(c[nt], u0, u1, u2, u3, b0, b1);
            }
        }
        __syncthreads();
        if (cc + 2 < 4) {
            #pragma unroll
            for (int i = 0; i < 4; i++) {
                int row = srow + i*32;
                cp16(&T[(cc&1)*128*T_S + row*T_S + sc4], pw + (pb+row)*DP + (cc+2)*32 + sc4);
            }
            CP_COMMIT();
        }
    }

    s0 += __shfl_xor_sync(0xffffffffu, s0, 1); s0 += __shfl_xor_sync(0xffffffffu, s0, 2);
    q0 += __shfl_xor_sync(0xffffffffu, q0, 1); q0 += __shfl_xor_sync(0xffffffffu, q0, 2);
    s1 += __shfl_xor_sync(0xffffffffu, s1, 1); s1 += __shfl_xor_sync(0xffffffffu, s1, 2);
    q1 += __shfl_xor_sync(0xffffffffu, q1, 1); q1 += __shfl_xor_sync(0xffffffffu, q1, 2);

    float mu0 = s0 * (1.f/DP), mu1 = s1 * (1.f/DP);
    float rinv0 = rsqrtf(q0*(1.f/DP) - mu0*mu0 + 1e-5f);
    float rinv1 = rsqrtf(q1*(1.f/DP) - mu1*mu1 + 1e-5f);
    float ab0 = ab[pb + r0], ab1 = ab[pb + r0 + 8];

    float* Ss = T;
    #pragma unroll
    for (int nt = 0; nt < 2; nt++) {
        #pragma unroll
        for (int j = 0; j < 2; j++) {
            int h = nt*8 + tig*2 + j;
            float Th = g_T[h], Uh = g_U[h];
            Ss[(r0    )*17 + h] = rinv0*(c[nt][j  ] - mu0*Th) + Uh + ab0;
            Ss[(r0 + 8)*17 + h] = rinv1*(c[nt][2+j] - mu1*Th) + Uh + ab1;
        }
    }
    __syncthreads();
    for (int l = t; l < 2048; l += 256) {
        int h = l >> 7, r = l & 127;
        g_scores[(size_t)h*NN + pb + r] = Ss[r*17 + h];
    }
}

__global__ __launch_bounds__(256) void fused_pb_kernel(
    const float* __restrict__ X,
    const float* __restrict__ Wq, const float* __restrict__ bq,
    const float* __restrict__ Wk, const float* __restrict__ Wv,
    const float* __restrict__ Wg,
    const float* __restrict__ pw, const float* __restrict__ ab)
{
    extern __shared__ float smem[];
    int bid = blockIdx.x;
    if (bid < 1024) {
        int sel = bid >> 8;
        int rem = bid & 255;
        const float* B = (sel==0) ? Wq : (sel==1) ? Wk : (sel==2) ? Wv : Wg;
        proj_body(smem, X, B, bq, sel, rem & 15, rem >> 4);
    } else {
        bias_body(smem, pw, ab, bid - 1024);
    }
}

// ---------------- attn v4 (unchanged from R8) ----------------
#define KS  68
#define VS  72
#define BBS 68
#define PSS 68

__device__ __forceinline__ void attn_stage(float* Kc, float* Vc, float* Bc,
    const float* bsrc, int h, int c, int t)
{
    const int buf = c & 1;
    const int jc = c * 64;
    float* Kb = Kc + buf*64*KS;
    float* Vb = Vc + buf*64*VS;
    float* Bb = Bc + buf*128*BBS;
    #pragma unroll
    for (int i = 0; i < 4; i++) {
        int l = t*4 + i*1024;
        int r = l >> 6, d = l & 63;
        cp16(Kb + r*KS + d, g_k + (size_t)(jc+r)*INNER + h*DH + d);
        cp16(Vb + r*VS + d, g_v + (size_t)(jc+r)*INNER + h*DH + d);
    }
    const int br = t >> 4, bc4 = (t & 15) * 4;
    const float* bs = bsrc + jc;
    #pragma unroll
    for (int j = 0; j < 8; j++) {
        int row = br + j*16;
        cp16(Bb + row*BBS + bc4, bs + (size_t)row*NTOK + bc4);
    }
    CP_COMMIT();
}

__global__ __launch_bounds__(256, 1) void attn4_kernel()
{
    extern __shared__ float sm2[];
    float* Kc = sm2;
    float* Vc = Kc + 2*64*KS;
    float* Bc = Vc + 2*64*VS;
    float* Ps = Bc + 2*128*BBS;

    const int t = threadIdx.x;
    const int h = blockIdx.y;
    const int i0 = blockIdx.x * 128;
    const int wid = t >> 5, lane = t & 31;
    const int g = lane >> 2, tig = lane & 3;
    const int R0 = wid * 16;
    const float* bsrc = g_scores + (size_t)h * NN + (size_t)i0 * NTOK;

    attn_stage(Kc, Vc, Bc, bsrc, h, 0, t);

    uint32_t qf[8][4];
    {
        const float* q0 = g_q + (size_t)(i0 + R0 + g    ) * INNER + h*DH;
        const float* q1 = g_q + (size_t)(i0 + R0 + g + 8) * INNER + h*DH;
        #pragma unroll
        for (int kk = 0; kk < 8; kk++) {
            qf[kk][0] = __float_as_uint(q0[kk*8 + tig]);
            qf[kk][1] = __float_as_uint(q1[kk*8 + tig]);
            qf[kk][2] = __float_as_uint(q0[kk*8 + tig + 4]);
            qf[kk][3] = __float_as_uint(q1[kk*8 + tig + 4]);
        }
    }

    attn_stage(Kc, Vc, Bc, bsrc, h, 1, t);

    float oc[8][4];
    #pragma unroll
    for (int nt = 0; nt < 8; nt++)
        #pragma unroll
        for (int j = 0; j < 4; j++) oc[nt][j] = 0.f;
    float m0v = -1e30f, m1v = -1e30f, l0v = 0.f, l1v = 0.f;

    for (int c = 0; c < 16; c++) {
        if (c < 15) asm volatile("cp.async.wait_group 1;");
        else        asm volatile("cp.async.wait_group 0;");
        __syncthreads();
        const float* Kb = Kc + (c&1)*64*KS;
        const float* Vb = Vc + (c&1)*64*VS;
        const float* Bcur = Bc + (c&1)*128*BBS;

        float sc[8][4];
        #pragma unroll
        for (int nt = 0; nt < 8; nt++)
            #pragma unroll
            for (int j = 0; j < 4; j++) sc[nt][j] = 0.f;
        #pragma unroll
        for (int kk = 0; kk < 8; kk++) {
            #pragma unroll
            for (int nt = 0; nt < 8; nt++) {
                uint32_t b0 = __float_as_uint(Kb[(nt*8+g)*KS + kk*8+tig]);
                uint32_t b1 = __float_as_uint(Kb[(nt*8+g)*KS + kk*8+tig+4]);
                mma_tf32(sc[nt], qf[kk][0], qf[kk][1], qf[kk][2], qf[kk][3], b0, b1);
            }
        }

        float rm0 = -1e30f, rm1 = -1e30f;
        #pragma unroll
        for (int nt = 0; nt < 8; nt++) {
            int cb = nt*8 + tig*2;
            sc[nt][0] = sc[nt][0]*0.125f + Bcur[(R0+g  )*BBS + cb];
            sc[nt][1] = sc[nt][1]*0.125f + Bcur[(R0+g  )*BBS + cb+1];
            sc[nt][2] = sc[nt][2]*0.125f + Bcur[(R0+g+8)*BBS + cb];
            sc[nt][3] = sc[nt][3]*0.125f + Bcur[(R0+g+8)*BBS + cb+1];
            rm0 = fmaxf(rm0, fmaxf(sc[nt][0], sc[nt][1]));
            rm1 = fmaxf(rm1, fmaxf(sc[nt][2], sc[nt][3]));
        }
        rm0 = fmaxf(rm0, __shfl_xor_sync(0xffffffffu, rm0, 1));
        rm0 = fmaxf(rm0, __shfl_xor_sync(0xffffffffu, rm0, 2));
        rm1 = fmaxf(rm1, __shfl_xor_sync(0xffffffffu, rm1, 1));
        rm1 = fmaxf(rm1, __shfl_xor_sync(0xffffffffu, rm1, 2));

        float mn0 = fmaxf(m0v, rm0), mn1 = fmaxf(m1v, rm1);
        float al0 = __expf(m0v - mn0), al1 = __expf(m1v - mn1);
        m0v = mn0; m1v = mn1;

        float ls0 = 0.f, ls1 = 0.f;
        #pragma unroll
        for (int nt = 0; nt < 8; nt++) {
            int cb = nt*8 + tig*2;
            float p0 = __expf(sc[nt][0] - mn0);
            float p1 = __expf(sc[nt][1] - mn0);
            float p2 = __expf(sc[nt][2] - mn1);
            float p3 = __expf(sc[nt][3] - mn1);
            ls0 += p0 + p1; ls1 += p2 + p3;
            Ps[(R0+g  )*PSS + cb  ] = to_tf32(p0);
            Ps[(R0+g  )*PSS + cb+1] = to_tf32(p1);
            Ps[(R0+g+8)*PSS + cb  ] = to_tf32(p2);
            Ps[(R0+g+8)*PSS + cb+1] = to_tf32(p3);
        }
        ls0 += __shfl_xor_sync(0xffffffffu, ls0, 1);
        ls0 += __shfl_xor_sync(0xffffffffu, ls0, 2);
        ls1 += __shfl_xor_sync(0xffffffffu, ls1, 1);
        ls1 += __shfl_xor_sync(0xffffffffu, ls1, 2);
        l0v = l0v*al0 + ls0;
        l1v = l1v*al1 + ls1;
        #pragma unroll
        for (int nt = 0; nt < 8; nt++) {
            oc[nt][0] *= al0; oc[nt][1] *= al0;
            oc[nt][2] *= al1; oc[nt][3] *= al1;
        }
        __syncwarp();

        #pragma unroll
        for (int kk = 0; kk < 8; kk++) {
            int kb = kk*8;
            uint32_t a0 = __float_as_uint(Ps[(R0+g  )*PSS + kb+tig]);
            uint32_t a1 = __float_as_uint(Ps[(R0+g+8)*PSS + kb+tig]);
            uint32_t a2 = __float_as_uint(Ps[(R0+g  )*PSS + kb+tig+4]);
            uint32_t a3 = __float_as_uint(Ps[(R0+g+8)*PSS + kb+tig+4]);
            #pragma unroll
            for (int nt = 0; nt < 8; nt++) {
                uint32_t b0 = __float_as_uint(Vb[(kb+tig  )*VS + nt*8+g]);
                uint32_t b1 = __float_as_uint(Vb[(kb+tig+4)*VS + nt*8+g]);
                mma_tf32(oc[nt], a0, a1, a2, a3, b0, b1);
            }
        }
        __syncthreads();
        if (c + 2 < 16) attn_stage(Kc, Vc, Bc, bsrc, h, c + 2, t);
    }

    float inv0 = 1.f/l0v, inv1 = 1.f/l1v;
    const float* gg0 = g_g + (size_t)(i0+R0+g    )*INNER + h*DH;
    const float* gg1 = g_g + (size_t)(i0+R0+g + 8)*INNER + h*DH;
    #pragma unroll
    for (int nt = 0; nt < 8; nt++) {
        int cb = nt*8 + tig*2;
        float2 gv0 = *(const float2*)(gg0 + cb);
        float2 gv1 = *(const float2*)(gg1 + cb);
        float s00 = 1.f/(1.f + __expf(-gv0.x));
        float s01 = 1.f/(1.f + __expf(-gv0.y));
        float s10 = 1.f/(1.f + __expf(-gv1.x));
        float s11 = 1.f/(1.f + __expf(-gv1.y));
        *(float2*)(g_attnout + (size_t)(i0+R0+g  )*INNER + h*DH + cb) =
            make_float2(oc[nt][0]*inv0*s00, oc[nt][1]*inv0*s01);
        *(float2*)(g_attnout + (size_t)(i0+R0+g+8)*INNER + h*DH + cb) =
            make_float2(oc[nt][2]*inv1*s10, oc[nt][3]*inv1*s11);
    }
}

// ---------------- outproj v3: BM=32 BN=64 BK=32, cp.async 3-stage ----------------
#define OA_S 36
#define OB_S 72
__global__ __launch_bounds__(256) void outproj3_kernel(
    const float* __restrict__ A, const float* __restrict__ B, float* __restrict__ C)
{
    __shared__ __align__(16) float As[3][32*OA_S];
    __shared__ __align__(16) float Bs[3][32*OB_S];

    const int t = threadIdx.x;
    const int m0 = blockIdx.y * 32;
    const int n0 = blockIdx.x * 64;
    const int wid = t >> 5, lane = t & 31;
    const int wm = wid & 1, wn = wid >> 1;
    const int g = lane >> 2, tig = lane & 3;
    const int R0 = wm * 16, C0 = wn * 16;

    float c[2][4];
    #pragma unroll
    for (int nt = 0; nt < 2; nt++)
        #pragma unroll
        for (int j = 0; j < 4; j++) c[nt][j] = 0.f;

    const int ar = t >> 3, ac4 = (t & 7) * 4;
    const int br = t >> 4, bc4 = (t & 15) * 4;

    #pragma unroll
    for (int s = 0; s < 3; s++) {
        cp16(&As[s][ar*OA_S + ac4], A + (size_t)(m0+ar)*INNER + s*32 + ac4);
        #pragma unroll
        for (int i = 0; i < 2; i++) {
            int row = br + i*16;
            cp16(&Bs[s][row*OB_S + bc4], B + (size_t)(s*32+row)*DS + n0 + bc4);
        }
        CP_COMMIT();
    }

    for (int cc = 0; cc < 32; cc++) {
        if (cc < 30)      asm volatile("cp.async.wait_group 2;");
        else if (cc == 30) asm volatile("cp.async.wait_group 1;");
        else               asm volatile("cp.async.wait_group 0;");
        __syncthreads();
        const float* Ab = As[cc % 3];
        const float* Bb = Bs[cc % 3];

        #pragma unroll
        for (int kk = 0; kk < 4; kk++) {
            int kb = kk*8;
            uint32_t a0 = __float_as_uint(to_tf32(Ab[(R0+g  )*OA_S + kb+tig]));
            uint32_t a1 = __float_as_uint(to_tf32(Ab[(R0+g+8)*OA_S + kb+tig]));
            uint32_t a2 = __float_as_uint(to_tf32(Ab[(R0+g  )*OA_S + kb+tig+4]));
            uint32_t a3 = __float_as_uint(to_tf32(Ab[(R0+g+8)*OA_S + kb+tig+4]));
            #pragma unroll
            for (int nt = 0; nt < 2; nt++) {
                uint32_t b0 = __float_as_uint(to_tf32(Bb[(kb+tig  )*OB_S + C0 + nt*8 + g]));
                uint32_t b1 = __float_as_uint(to_tf32(Bb[(kb+tig+4)*OB_S + C0 + nt*8 + g]));
                mma_tf32(c[nt], a0, a1, a2, a3, b0, b1);
            }
        }
        __syncthreads();
        if (cc + 3 < 32) {
            int s = cc % 3, k0 = (cc+3)*32;
            cp16(&As[s][ar*OA_S + ac4], A + (size_t)(m0+ar)*INNER + k0 + ac4);
            #pragma unroll
            for (int i = 0; i < 2; i++) {
                int row = br + i*16;
                cp16(&Bs[s][row*OB_S + bc4], B + (size_t)(k0+row)*DS + n0 + bc4);
            }
            CP_COMMIT();
        }
    }

    #pragma unroll
    for (int nt = 0; nt < 2; nt++) {
        int n = n0 + C0 + nt*8 + tig*2;
        int r0 = m0 + R0 + g;
        *(float2*)(C + (size_t)r0*DS + n)     = make_float2(c[nt][0], c[nt][1]);
        *(float2*)(C + (size_t)(r0+8)*DS + n) = make_float2(c[nt][2], c[nt][3]);
    }
}

// ---------------- launcher ----------------
extern "C" void kernel_launch(void* const* d_in, const int* in_sizes, int n_in,
                              void* d_out, int out_size)
{
    const float* x     = (const float*)d_in[0];
    const float* pw    = (const float*)d_in[1];
    const float* ab    = (const float*)d_in[2];
    const float* gamma = (const float*)d_in[3];
    const float* beta  = (const float*)d_in[4];
    const float* Wb    = (const float*)d_in[5];
    const float* Wq    = (const float*)d_in[6];
    const float* bq    = (const float*)d_in[7];
    const float* Wk    = (const float*)d_in[8];
    const float* Wv    = (const float*)d_in[9];
    const float* Wg    = (const float*)d_in[10];
    const float* Wo    = (const float*)d_in[11];
    float* out = (float*)d_out;

    float* dao; cudaGetSymbolAddress((void**)&dao, g_attnout);

    prep_kernel<<<1, 256>>>(gamma, beta, Wb);

    const int pb_smem = (128*WS_S + 2*128*T_S) * 4;   // 49152 -> 4 CTAs/SM (bias); proj fits in 36.9KB
    cudaFuncSetAttribute(fused_pb_kernel, cudaFuncAttributeMaxDynamicSharedMemorySize, pb_smem);
    fused_pb_kernel<<<1024 + NN/128, 256, pb_smem>>>(x, Wq, bq, Wk, Wv, Wg, pw, ab);

    const int attn_smem = (2*64*KS + 2*64*VS + 2*128*BBS + 128*PSS) * 4;  // 176128
    cudaFuncSetAttribute(attn4_kernel, cudaFuncAttributeMaxDynamicSharedMemorySize, attn_smem);
    attn4_kernel<<<dim3(NTOK/128, NH), 256, attn_smem>>>();

    outproj3_kernel<<<dim3(DS/64, NTOK/32), 256>>>(dao, Wo, out);
}